// round 16
// baseline (speedup 1.0000x reference)
#include <cuda_runtime.h>
#include <stdint.h>

// TopK mask: out = x * (x in top-k of its row), ties -> lowest index.
// R16 = R14 hot/cold row logic + 2-rows-per-CTA software pipeline:
// cp.async prefetches row1 into smem while row0 is loaded to registers and
// processed; row1 is then processed with no exposed DRAM latency.

#define F_DIM 4096
#define TPB   256
#define CAP   192   // candidate capacity; count(x>=2.0) ~ 93 +- 9.5 for N(0,1)

static __device__ __forceinline__ unsigned f2key(unsigned u) {
    return u ^ ((unsigned)((int)u >> 31) | 0x80000000u);
}

__global__ __launch_bounds__(TPB, 8)
void topk_mask_kernel(const float* __restrict__ x,
                      const int*   __restrict__ kptr,
                      int kfallback, int B,
                      float* __restrict__ out)
{
    const int tid  = threadIdx.x;
    const int lane = tid & 31;
    const int wid  = tid >> 5;

    __shared__ __align__(16) float s_buf[F_DIM];      // row1 prefetch buffer
    __shared__ __align__(16) float s_cand[CAP + 4];   // cold path reuses as keys
    __shared__ __align__(16) unsigned s_wcnt[8];
    __shared__ unsigned s_warp[8][4];
    __shared__ unsigned s_ctrl[8];  // [0]=Kstar [1]=winner cnt [2]=c_ge [3]=c_gt [7]=cand ctr

    const int half = gridDim.x;
    const size_t r0 = blockIdx.x;
    const size_t r1 = (size_t)blockIdx.x + (size_t)half;
    const bool has_r1 = (r1 < (size_t)B);

    const int kv = (kptr != nullptr) ? __ldg(kptr) : kfallback;

    if (kv <= 0) {
        float4 z; z.x = z.y = z.z = z.w = 0.0f;
        float4* o0 = reinterpret_cast<float4*>(out) + r0 * (F_DIM / 4);
        #pragma unroll
        for (int i = 0; i < 4; ++i) __stcs(&o0[tid + i * 256], z);
        if (has_r1) {
            float4* o1 = reinterpret_cast<float4*>(out) + r1 * (F_DIM / 4);
            #pragma unroll
            for (int i = 0; i < 4; ++i) __stcs(&o1[tid + i * 256], z);
        }
        return;
    }
    if (kv >= F_DIM) {
        const float4* x0 = reinterpret_cast<const float4*>(x) + r0 * (F_DIM / 4);
        float4*       o0 = reinterpret_cast<float4*>(out)     + r0 * (F_DIM / 4);
        #pragma unroll
        for (int i = 0; i < 4; ++i) __stcs(&o0[tid + i * 256], __ldg(x0 + tid + i * 256));
        if (has_r1) {
            const float4* x1 = reinterpret_cast<const float4*>(x) + r1 * (F_DIM / 4);
            float4*       o1 = reinterpret_cast<float4*>(out)     + r1 * (F_DIM / 4);
            #pragma unroll
            for (int i = 0; i < 4; ++i) __stcs(&o1[tid + i * 256], __ldg(x1 + tid + i * 256));
        }
        return;
    }
    const unsigned K = (unsigned)kv;
    const float T = 2.0f;

    // ---- per-row processing (hot: fixed-threshold rank select; cold: exact
    //      streaming key-domain radix select). Uniform control flow. ----
    auto process = [&](float4 a0, float4 a1, float4 a2, float4 a3,
                       const uint4* __restrict__ xu,
                       float4* __restrict__ orow) {
        bool fallback = false;
        unsigned n_c;
        {
            unsigned cnt = 0;
            cnt += (a0.x >= T); cnt += (a0.y >= T); cnt += (a0.z >= T); cnt += (a0.w >= T);
            cnt += (a1.x >= T); cnt += (a1.y >= T); cnt += (a1.z >= T); cnt += (a1.w >= T);
            cnt += (a2.x >= T); cnt += (a2.y >= T); cnt += (a2.z >= T); cnt += (a2.w >= T);
            cnt += (a3.x >= T); cnt += (a3.y >= T); cnt += (a3.z >= T); cnt += (a3.w >= T);

            unsigned incl = cnt;
            #pragma unroll
            for (int d = 1; d < 32; d <<= 1) {
                unsigned nb = __shfl_up_sync(0xffffffffu, incl, d);
                if (lane >= d) incl += nb;
            }
            if (lane == 31) s_wcnt[wid] = incl;
            if (tid == 0)   s_ctrl[1] = 0u;
            __syncthreads();

            uint4 w0 = reinterpret_cast<const uint4*>(s_wcnt)[0];
            uint4 w1 = reinterpret_cast<const uint4*>(s_wcnt)[1];
            unsigned wv[8] = { w0.x, w0.y, w0.z, w0.w, w1.x, w1.y, w1.z, w1.w };
            unsigned base = 0, tot = 0;
            #pragma unroll
            for (int w = 0; w < 8; ++w) {
                tot += wv[w];
                if (w < wid) base += wv[w];
            }
            n_c = tot;
            if (n_c < K || n_c > CAP) {
                fallback = true;                       // uniform across block
            } else {
                unsigned pos = base + (incl - cnt);
                if (a0.x >= T) s_cand[pos++] = a0.x;
                if (a0.y >= T) s_cand[pos++] = a0.y;
                if (a0.z >= T) s_cand[pos++] = a0.z;
                if (a0.w >= T) s_cand[pos++] = a0.w;
                if (a1.x >= T) s_cand[pos++] = a1.x;
                if (a1.y >= T) s_cand[pos++] = a1.y;
                if (a1.z >= T) s_cand[pos++] = a1.z;
                if (a1.w >= T) s_cand[pos++] = a1.w;
                if (a2.x >= T) s_cand[pos++] = a2.x;
                if (a2.y >= T) s_cand[pos++] = a2.y;
                if (a2.z >= T) s_cand[pos++] = a2.z;
                if (a2.w >= T) s_cand[pos++] = a2.w;
                if (a3.x >= T) s_cand[pos++] = a3.x;
                if (a3.y >= T) s_cand[pos++] = a3.y;
                if (a3.z >= T) s_cand[pos++] = a3.z;
                if (a3.w >= T) s_cand[pos++] = a3.w;
                if (tid == 0) {                        // pad to x4 for float4 loads
                    s_cand[n_c]     = __int_as_float(0xff800000);
                    s_cand[n_c + 1] = __int_as_float(0xff800000);
                    s_cand[n_c + 2] = __int_as_float(0xff800000);
                    s_cand[n_c + 3] = __int_as_float(0xff800000);
                }
            }
        }

        if (!fallback) {
            __syncthreads();
            if ((unsigned)tid < n_c) {
                float c = s_cand[tid];
                unsigned gt = 0;
                const float4* p4 = reinterpret_cast<const float4*>(s_cand);
                const unsigned np = (n_c + 3u) >> 2;
                #pragma unroll 4
                for (unsigned jp = 0; jp < np; ++jp) {
                    float4 w4 = p4[jp];
                    gt += (w4.x > c);
                    gt += (w4.y > c);
                    gt += (w4.z > c);
                    gt += (w4.w > c);
                }
                if (gt == K - 1u) {
                    atomicAdd(&s_ctrl[1], 1u);
                    s_ctrl[0] = __float_as_uint(c);    // duplicates: identical bits
                }
            }
            __syncthreads();

            const unsigned m = s_ctrl[1];
            if (m >= 1u) {
                const float Ks = __uint_as_float(s_ctrl[0]);
                if (m == 1u) {
                    float4 o;
                    o.x = (a0.x >= Ks) ? a0.x : 0.0f;
                    o.y = (a0.y >= Ks) ? a0.y : 0.0f;
                    o.z = (a0.z >= Ks) ? a0.z : 0.0f;
                    o.w = (a0.w >= Ks) ? a0.w : 0.0f;
                    __stcs(&orow[tid], o);
                    o.x = (a1.x >= Ks) ? a1.x : 0.0f;
                    o.y = (a1.y >= Ks) ? a1.y : 0.0f;
                    o.z = (a1.z >= Ks) ? a1.z : 0.0f;
                    o.w = (a1.w >= Ks) ? a1.w : 0.0f;
                    __stcs(&orow[tid + 256], o);
                    o.x = (a2.x >= Ks) ? a2.x : 0.0f;
                    o.y = (a2.y >= Ks) ? a2.y : 0.0f;
                    o.z = (a2.z >= Ks) ? a2.z : 0.0f;
                    o.w = (a2.w >= Ks) ? a2.w : 0.0f;
                    __stcs(&orow[tid + 512], o);
                    o.x = (a3.x >= Ks) ? a3.x : 0.0f;
                    o.y = (a3.y >= Ks) ? a3.y : 0.0f;
                    o.z = (a3.z >= Ks) ? a3.z : 0.0f;
                    o.w = (a3.w >= Ks) ? a3.w : 0.0f;
                    __stcs(&orow[tid + 768], o);
                    return;
                }
                // m > 1: keep lowest-index element == Ks
                unsigned mc = 0xFFFFFFFFu;
                {
                    const unsigned c0 = (unsigned)(tid << 2);
                    if (a0.x == Ks) mc = min(mc, c0 + 0u);
                    if (a0.y == Ks) mc = min(mc, c0 + 1u);
                    if (a0.z == Ks) mc = min(mc, c0 + 2u);
                    if (a0.w == Ks) mc = min(mc, c0 + 3u);
                    if (a1.x == Ks) mc = min(mc, c0 + 1024u);
                    if (a1.y == Ks) mc = min(mc, c0 + 1025u);
                    if (a1.z == Ks) mc = min(mc, c0 + 1026u);
                    if (a1.w == Ks) mc = min(mc, c0 + 1027u);
                    if (a2.x == Ks) mc = min(mc, c0 + 2048u);
                    if (a2.y == Ks) mc = min(mc, c0 + 2049u);
                    if (a2.z == Ks) mc = min(mc, c0 + 2050u);
                    if (a2.w == Ks) mc = min(mc, c0 + 2051u);
                    if (a3.x == Ks) mc = min(mc, c0 + 3072u);
                    if (a3.y == Ks) mc = min(mc, c0 + 3073u);
                    if (a3.z == Ks) mc = min(mc, c0 + 3074u);
                    if (a3.w == Ks) mc = min(mc, c0 + 3075u);
                }
                mc = __reduce_min_sync(0xffffffffu, mc);
                if (lane == 0) s_wcnt[wid] = mc;
                __syncthreads();
                unsigned Ccut = 0xFFFFFFFFu;
                #pragma unroll
                for (int w = 0; w < 8; ++w) Ccut = min(Ccut, s_wcnt[w]);

                {
                    const unsigned c0 = (unsigned)(tid << 2);
                    float4 o;
                    o.x = ((a0.x > Ks) || (a0.x == Ks && (c0 + 0u)    <= Ccut)) ? a0.x : 0.0f;
                    o.y = ((a0.y > Ks) || (a0.y == Ks && (c0 + 1u)    <= Ccut)) ? a0.y : 0.0f;
                    o.z = ((a0.z > Ks) || (a0.z == Ks && (c0 + 2u)    <= Ccut)) ? a0.z : 0.0f;
                    o.w = ((a0.w > Ks) || (a0.w == Ks && (c0 + 3u)    <= Ccut)) ? a0.w : 0.0f;
                    __stcs(&orow[tid], o);
                    o.x = ((a1.x > Ks) || (a1.x == Ks && (c0 + 1024u) <= Ccut)) ? a1.x : 0.0f;
                    o.y = ((a1.y > Ks) || (a1.y == Ks && (c0 + 1025u) <= Ccut)) ? a1.y : 0.0f;
                    o.z = ((a1.z > Ks) || (a1.z == Ks && (c0 + 1026u) <= Ccut)) ? a1.z : 0.0f;
                    o.w = ((a1.w > Ks) || (a1.w == Ks && (c0 + 1027u) <= Ccut)) ? a1.w : 0.0f;
                    __stcs(&orow[tid + 256], o);
                    o.x = ((a2.x > Ks) || (a2.x == Ks && (c0 + 2048u) <= Ccut)) ? a2.x : 0.0f;
                    o.y = ((a2.y > Ks) || (a2.y == Ks && (c0 + 2049u) <= Ccut)) ? a2.y : 0.0f;
                    o.z = ((a2.z > Ks) || (a2.z == Ks && (c0 + 2050u) <= Ccut)) ? a2.z : 0.0f;
                    o.w = ((a2.w > Ks) || (a2.w == Ks && (c0 + 2051u) <= Ccut)) ? a2.w : 0.0f;
                    __stcs(&orow[tid + 512], o);
                    o.x = ((a3.x > Ks) || (a3.x == Ks && (c0 + 3072u) <= Ccut)) ? a3.x : 0.0f;
                    o.y = ((a3.y > Ks) || (a3.y == Ks && (c0 + 3073u) <= Ccut)) ? a3.y : 0.0f;
                    o.z = ((a3.z > Ks) || (a3.z == Ks && (c0 + 3074u) <= Ccut)) ? a3.z : 0.0f;
                    o.w = ((a3.w > Ks) || (a3.w == Ks && (c0 + 3075u) <= Ccut)) ? a3.w : 0.0f;
                    __stcs(&orow[tid + 768], o);
                }
                return;
            }
            // m == 0: tie group straddles K -> cold path
        }

        // -------- COLD PATH: exact streaming key-domain radix select --------
        __syncthreads();
        unsigned* s_ckey = reinterpret_cast<unsigned*>(s_cand);

        unsigned lo = 0u, cnt_lo = F_DIM, cnt_hi1 = 0u;
        int shift = 32;

        #pragma unroll 1
        while (cnt_lo - cnt_hi1 > CAP && shift > 0) {
            unsigned q = 1u << (shift - 2);
            unsigned t1 = lo + q, t2 = lo + 2u * q, t3 = lo + 3u * q;
            unsigned c1 = 0, c2 = 0, c3 = 0;
            #pragma unroll 1
            for (int i = 0; i < 4; ++i) {
                uint4 b = __ldg(xu + tid + i * 256);
                unsigned k;
                k = f2key(b.x); c1 += (k >= t1); c2 += (k >= t2); c3 += (k >= t3);
                k = f2key(b.y); c1 += (k >= t1); c2 += (k >= t2); c3 += (k >= t3);
                k = f2key(b.z); c1 += (k >= t1); c2 += (k >= t2); c3 += (k >= t3);
                k = f2key(b.w); c1 += (k >= t1); c2 += (k >= t2); c3 += (k >= t3);
            }
            c1 = __reduce_add_sync(0xffffffffu, c1);
            c2 = __reduce_add_sync(0xffffffffu, c2);
            c3 = __reduce_add_sync(0xffffffffu, c3);
            if (lane == 0) { s_warp[wid][0] = c1; s_warp[wid][1] = c2; s_warp[wid][2] = c3; }
            __syncthreads();
            unsigned C1 = 0, C2 = 0, C3 = 0;
            #pragma unroll
            for (int w = 0; w < 8; ++w) { C1 += s_warp[w][0]; C2 += s_warp[w][1]; C3 += s_warp[w][2]; }
            __syncthreads();
            if      (C3 >= K) { lo = t3; cnt_lo = C3; }
            else if (C2 >= K) { lo = t2; cnt_lo = C2; cnt_hi1 = C3; }
            else if (C1 >= K) { lo = t1; cnt_lo = C1; cnt_hi1 = C2; }
            else              {                      cnt_hi1 = C1; }
            shift -= 2;
        }

        unsigned Kstar, c_ge, c_gt;
        if (shift == 0) {
            Kstar = lo; c_ge = cnt_lo; c_gt = cnt_hi1;
        } else {
            if (tid == 0) s_ctrl[7] = 0u;
            __syncthreads();
            const unsigned hib = lo + ((1u << shift) - 1u);
            #pragma unroll 1
            for (int i = 0; i < 4; ++i) {
                uint4 b = __ldg(xu + tid + i * 256);
                #pragma unroll
                for (int j = 0; j < 4; ++j) {
                    unsigned k = f2key(j == 0 ? b.x : j == 1 ? b.y : j == 2 ? b.z : b.w);
                    bool in = (k >= lo) && (k <= hib);
                    unsigned mk = __ballot_sync(0xffffffffu, in);
                    unsigned base = 0u;
                    if (lane == 0) base = atomicAdd(&s_ctrl[7], (unsigned)__popc(mk));
                    base = __shfl_sync(0xffffffffu, base, 0);
                    if (in) {
                        unsigned p = base + (unsigned)__popc(mk & ((1u << lane) - 1u));
                        if (p < CAP) s_ckey[p] = k;
                    }
                }
            }
            __syncthreads();

            const unsigned nc = s_ctrl[7];
            const unsigned A  = cnt_hi1;
            if ((unsigned)tid < nc) {
                unsigned ck = s_ckey[tid];
                unsigned gt = 0, ge = 0;
                #pragma unroll 4
                for (unsigned j = 0; j < nc; ++j) {
                    unsigned vv = s_ckey[j];
                    gt += (vv >  ck);
                    ge += (vv >= ck);
                }
                unsigned GT = A + gt, GE = A + ge;
                if (GT < K && GE >= K) { s_ctrl[0] = ck; s_ctrl[2] = GE; s_ctrl[3] = GT; }
            }
            __syncthreads();
            Kstar = s_ctrl[0]; c_ge = s_ctrl[2]; c_gt = s_ctrl[3];
        }

        unsigned Ccut = 0xFFFFFFFFu;
        {
            unsigned budget = K - c_gt;
            unsigned c_eq   = c_ge - c_gt;
            if (budget < c_eq) {
                int loB = 0, hiB = F_DIM - 1;
                #pragma unroll 1
                while (loB < hiB) {
                    int mid = (loB + hiB) >> 1;
                    unsigned cc = 0;
                    #pragma unroll 1
                    for (int i = 0; i < 4; ++i) {
                        uint4 b = __ldg(xu + tid + i * 256);
                        unsigned col0 = (unsigned)((i << 10) + (tid << 2));
                        cc += (f2key(b.x) == Kstar && (int)(col0 + 0u) <= mid) ? 1u : 0u;
                        cc += (f2key(b.y) == Kstar && (int)(col0 + 1u) <= mid) ? 1u : 0u;
                        cc += (f2key(b.z) == Kstar && (int)(col0 + 2u) <= mid) ? 1u : 0u;
                        cc += (f2key(b.w) == Kstar && (int)(col0 + 3u) <= mid) ? 1u : 0u;
                    }
                    cc = __reduce_add_sync(0xffffffffu, cc);
                    if (lane == 0) s_warp[wid][0] = cc;
                    __syncthreads();
                    unsigned Ct = 0;
                    #pragma unroll
                    for (int w = 0; w < 8; ++w) Ct += s_warp[w][0];
                    __syncthreads();
                    if (Ct >= budget) hiB = mid; else loB = mid + 1;
                }
                Ccut = (unsigned)loB;
            }
        }

        #pragma unroll 1
        for (int i = 0; i < 4; ++i) {
            uint4 b = __ldg(xu + tid + i * 256);
            unsigned col0 = (unsigned)((i << 10) + (tid << 2));
            unsigned k0 = f2key(b.x), k1 = f2key(b.y), k2 = f2key(b.z), k3 = f2key(b.w);
            uint4 o;
            o.x = ((k0 > Kstar) || (k0 == Kstar && (col0 + 0u) <= Ccut)) ? b.x : 0u;
            o.y = ((k1 > Kstar) || (k1 == Kstar && (col0 + 1u) <= Ccut)) ? b.y : 0u;
            o.z = ((k2 > Kstar) || (k2 == Kstar && (col0 + 2u) <= Ccut)) ? b.z : 0u;
            o.w = ((k3 > Kstar) || (k3 == Kstar && (col0 + 3u) <= Ccut)) ? b.w : 0u;
            __stcs(&reinterpret_cast<uint4*>(orow)[tid + i * 256], o);
        }
    };

    // ---- prefetch row1 into smem via cp.async (no data registers) ----
    if (has_r1) {
        const float4* x1 = reinterpret_cast<const float4*>(x) + r1 * (F_DIM / 4);
        float4* sb4 = reinterpret_cast<float4*>(s_buf);
        #pragma unroll
        for (int i = 0; i < 4; ++i) {
            unsigned sa = (unsigned)__cvta_generic_to_shared(&sb4[tid + i * 256]);
            asm volatile("cp.async.cg.shared.global [%0], [%1], 16;\n"
                         :: "r"(sa), "l"(x1 + tid + i * 256) : "memory");
        }
        asm volatile("cp.async.commit_group;\n" ::: "memory");
    }

    // ---- row 0: load to registers, process ----
    {
        const float4* x0 = reinterpret_cast<const float4*>(x) + r0 * (F_DIM / 4);
        float4 a0 = __ldg(x0 + tid);
        float4 a1 = __ldg(x0 + tid + 256);
        float4 a2 = __ldg(x0 + tid + 512);
        float4 a3 = __ldg(x0 + tid + 768);
        process(a0, a1, a2, a3,
                reinterpret_cast<const uint4*>(x) + r0 * (F_DIM / 4),
                reinterpret_cast<float4*>(out) + r0 * (F_DIM / 4));
    }

    // ---- row 1: wait prefetch, read from smem, process ----
    if (has_r1) {
        asm volatile("cp.async.wait_group 0;\n" ::: "memory");
        __syncthreads();   // prefetch visible + s_cand/s_ctrl reuse ordering
        float4* sb4 = reinterpret_cast<float4*>(s_buf);
        float4 b0 = sb4[tid];
        float4 b1 = sb4[tid + 256];
        float4 b2 = sb4[tid + 512];
        float4 b3 = sb4[tid + 768];
        process(b0, b1, b2, b3,
                reinterpret_cast<const uint4*>(x) + r1 * (F_DIM / 4),
                reinterpret_cast<float4*>(out) + r1 * (F_DIM / 4));
    }
}

extern "C" void kernel_launch(void* const* d_in, const int* in_sizes, int n_in,
                              void* d_out, int out_size)
{
    const float* x  = (const float*)d_in[0];
    const int*   kp = (n_in >= 2) ? (const int*)d_in[1] : nullptr;
    float* out = (float*)d_out;

    int B = in_sizes[0] / F_DIM;
    int half = (B + 1) / 2;
    topk_mask_kernel<<<half, TPB>>>(x, kp, 64, B, out);
}